// round 1
// baseline (speedup 1.0000x reference)
#include <cuda_runtime.h>
#include <stdint.h>

// ---------------------------------------------------------------------------
// Persistent fp32 RNN:  out[t] = tanh(x[t] @ Wi^T + h @ Wh^T),  h = out[t]
//
// Grid: 8 batch-groups (16 batches each) x 16 H-slice CTAs (32 outputs each)
//       = 128 CTAs, 1 CTA/SM (smem-bound) -> all co-resident.
// Per CTA, SMEM-resident:
//   Ws [768][32]  : rows 0..511 = Wh[j][k] transposed slice, rows 512..767 = Wi
//   Hd [768][36]  : duplicated pairs {v,v} of [h_t | x_t] per batch (16 batches)
//   Ps [8][16][34]: per-warp k-chunk partial sums
// Inner loop: per k, 3x LDS.128 + 8x fma.rn.f32x2 (8 j x 2 b per thread).
// Group sync: global atomic counter, monotonic across graph replays.
// ---------------------------------------------------------------------------

namespace {
constexpr int kT = 1024, kB = 128, kI = 256, kH = 512;
constexpr int KTOT = kH + kI;               // 768
constexpr int NG   = 8;                     // batch groups
constexpr int BG   = kB / NG;               // 16 batches / group
constexpr int NC   = 16;                    // CTAs per group (H slices)
constexpr int JC   = kH / NC;               // 32 outputs / CTA
constexpr int NTHR = 256;
constexpr int NWARP = NTHR / 32;            // 8 (one k-chunk per warp)
constexpr int KCH  = KTOT / NWARP;          // 96 k per chunk

constexpr int WS_STRIDE = JC;               // 32 floats / k-row
constexpr int HD_STRIDE = 36;               // 32 + 4 pad (16B-aligned rows)
constexpr int PS_STRIDE = 34;               // 32 + 2 pad

constexpr int OFF_WS = 0;
constexpr int OFF_HD = OFF_WS + KTOT * WS_STRIDE;             // 24576
constexpr int OFF_PS = OFF_HD + KTOT * HD_STRIDE;             // 52224
constexpr int SMEM_FLOATS = OFF_PS + NWARP * BG * PS_STRIDE;  // 56576
constexpr size_t SMEM_BYTES = size_t(SMEM_FLOATS) * 4;        // 226304 B
}

__device__ unsigned g_rnn_bar[NG];   // zero-init at load; monotonic forever

__device__ __forceinline__ void fma_f32x2(unsigned long long& acc,
                                          unsigned long long a,
                                          unsigned long long b) {
    asm("fma.rn.f32x2 %0, %1, %2, %0;" : "+l"(acc) : "l"(a), "l"(b));
}

__device__ __forceinline__ unsigned long long dup_f32(float v) {
    unsigned u = __float_as_uint(v);
    return (((unsigned long long)u) << 32) | (unsigned long long)u;
}

__global__ void __launch_bounds__(NTHR, 1)
rnn_persistent_kernel(const float* __restrict__ x,
                      const float* __restrict__ Wi,
                      const float* __restrict__ Wh,
                      float* __restrict__ out,
                      int write_tail)
{
    extern __shared__ float sm[];
    float* Ws   = sm + OFF_WS;
    float* Hdup = sm + OFF_HD;
    float* Ps   = sm + OFF_PS;

    const int tid = threadIdx.x;
    const int g   = blockIdx.x >> 4;    // batch group 0..7
    const int c   = blockIdx.x & 15;    // H slice    0..15
    const int bg0 = g * BG;
    const int jg0 = c * JC;

    // ---- prologue: stage weights (one-time) ------------------------------
    // Wh slice -> Ws rows [0,512), k-major, conflict-free STS
    for (int e = tid; e < JC * kH; e += NTHR) {
        int jl = e & (JC - 1);
        int k  = e >> 5;
        Ws[k * WS_STRIDE + jl] = Wh[(size_t)(jg0 + jl) * kH + k];
    }
    // Wi slice -> Ws rows [512,768)
    for (int e = tid; e < JC * kI; e += NTHR) {
        int jl = e & (JC - 1);
        int i  = e >> 5;
        Ws[(kH + i) * WS_STRIDE + jl] = Wi[(size_t)(jg0 + jl) * kI + i];
    }
    // h0 = 0 : zero Hd rows [0,512)
    for (int e = tid; e < kH * HD_STRIDE; e += NTHR) Hdup[e] = 0.f;
    // x[0] -> Hd rows [512,768), duplicated pairs
    {
        const int b16 = tid >> 4, l16 = tid & 15;
        const float* xp = x + (size_t)(bg0 + b16) * kI;
        #pragma unroll
        for (int i = 0; i < kI / 16; ++i) {
            int kk = l16 + 16 * i;
            float v = __ldg(xp + kk);
            *reinterpret_cast<unsigned long long*>(
                &Hdup[(kH + kk) * HD_STRIDE + 2 * b16]) = dup_f32(v);
        }
    }
    __syncthreads();

    // ---- per-thread tile -------------------------------------------------
    const int warp  = tid >> 5;          // k-chunk
    const int lane  = tid & 31;
    const int jq    = lane & 3;          // j octet: j in [jq*8, jq*8+8)
    const int bp    = lane >> 2;         // batch pair: b0 = 2*bp
    const int kbase = warp * KCH;
    const float* wbase = Ws   + (size_t)kbase * WS_STRIDE + jq * 8;
    const float* hbase = Hdup + (size_t)kbase * HD_STRIDE + bp * 4;

    for (int t = 0; t < kT; ++t) {
        unsigned long long a0=0,a1=0,a2=0,a3=0,a4=0,a5=0,a6=0,a7=0;

        // ---- inner: (h|x) . (Wh|Wi) over this warp's 96-k chunk ----------
        const float* wp = wbase;
        const float* hp = hbase;
        #pragma unroll 8
        for (int kk = 0; kk < KCH; ++kk) {
            const ulonglong2 w0 = *reinterpret_cast<const ulonglong2*>(wp);
            const ulonglong2 w1 = *reinterpret_cast<const ulonglong2*>(wp + 4);
            const ulonglong2 hh = *reinterpret_cast<const ulonglong2*>(hp);
            fma_f32x2(a0, w0.x, hh.x);  fma_f32x2(a1, w0.y, hh.x);
            fma_f32x2(a2, w1.x, hh.x);  fma_f32x2(a3, w1.y, hh.x);
            fma_f32x2(a4, w0.x, hh.y);  fma_f32x2(a5, w0.y, hh.y);
            fma_f32x2(a6, w1.x, hh.y);  fma_f32x2(a7, w1.y, hh.y);
            wp += WS_STRIDE;
            hp += HD_STRIDE;
        }
        __syncthreads();

        // ---- scatter partials to Ps --------------------------------------
        {
            unsigned long long acc[8] = {a0,a1,a2,a3,a4,a5,a6,a7};
            #pragma unroll
            for (int bi = 0; bi < 2; ++bi)
                #pragma unroll
                for (int jp = 0; jp < 4; ++jp) {
                    int b   = bp * 2 + bi;
                    int col = jq * 8 + jp * 2;
                    *reinterpret_cast<unsigned long long*>(
                        &Ps[(warp * BG + b) * PS_STRIDE + col]) = acc[jp + 4 * bi];
                }
        }
        // ---- prefetch x[t+1] into Hd rows [512,768) (no dependence) ------
        if (t + 1 < kT) {
            const int b16 = tid >> 4, l16 = tid & 15;
            const float* xp = x + (size_t)(t + 1) * kB * kI
                                + (size_t)(bg0 + b16) * kI;
            #pragma unroll
            for (int i = 0; i < kI / 16; ++i) {
                int kk = l16 + 16 * i;
                float v = __ldg(xp + kk);
                *reinterpret_cast<unsigned long long*>(
                    &Hdup[(kH + kk) * HD_STRIDE + 2 * b16]) = dup_f32(v);
            }
        }
        __syncthreads();

        // ---- reduce 8 partials, tanh, store output -----------------------
        {
            const int b  = tid >> 4;
            const int j0 = (tid & 15) * 2;
            float sx = 0.f, sy = 0.f;
            #pragma unroll
            for (int ks = 0; ks < NWARP; ++ks) {
                float2 p = *reinterpret_cast<const float2*>(
                    &Ps[(ks * BG + b) * PS_STRIDE + j0]);
                sx += p.x; sy += p.y;
            }
            float2 r;
            r.x = tanhf(sx);
            r.y = tanhf(sy);
            size_t o = (size_t)t * kB * kH + (size_t)(bg0 + b) * kH + jg0 + j0;
            *reinterpret_cast<float2*>(out + o) = r;
            if (t == kT - 1 && write_tail) {
                size_t ot = (size_t)kT * kB * kH
                          + (size_t)(bg0 + b) * kH + jg0 + j0;
                *reinterpret_cast<float2*>(out + ot) = r;
            }
        }
        if (t + 1 == kT) break;

        // ---- group barrier (16 CTAs), monotonic counter ------------------
        __threadfence();
        __syncthreads();
        if (tid == 0) {
            unsigned old = atomicAdd(&g_rnn_bar[g], 1u);
            unsigned target = ((old >> 4) + 1u) << 4;
            unsigned cur;
            do {
                asm volatile("ld.acquire.gpu.global.u32 %0, [%1];"
                             : "=r"(cur) : "l"(&g_rnn_bar[g]) : "memory");
            } while (cur < target);
        }
        __syncthreads();

        // ---- read back full h (all 16 batches) from out[t] ---------------
        {
            const int b16 = tid >> 4, l16 = tid & 15;
            const float* op = out + (size_t)t * kB * kH
                                  + (size_t)(bg0 + b16) * kH;
            #pragma unroll 8
            for (int i = 0; i < kH / 16; ++i) {
                int kk = l16 + 16 * i;
                float v = __ldcg(op + kk);
                *reinterpret_cast<unsigned long long*>(
                    &Hdup[kk * HD_STRIDE + 2 * b16]) = dup_f32(v);
            }
        }
        __syncthreads();
    }
}

extern "C" void kernel_launch(void* const* d_in, const int* in_sizes, int n_in,
                              void* d_out, int out_size) {
    const float* x  = (const float*)d_in[0];   // [T,B,I]
    const float* Wi = (const float*)d_in[1];   // [H,I]
    const float* Wh = (const float*)d_in[2];   // [H,H]
    float* out = (float*)d_out;

    const long long main_elems = (long long)kT * kB * kH;
    int write_tail = ((long long)out_size >= main_elems + (long long)kB * kH) ? 1 : 0;

    cudaFuncSetAttribute(rnn_persistent_kernel,
                         cudaFuncAttributeMaxDynamicSharedMemorySize,
                         (int)SMEM_BYTES);
    rnn_persistent_kernel<<<NG * NC, NTHR, SMEM_BYTES>>>(x, Wi, Wh, out, write_tail);
}